// round 5
// baseline (speedup 1.0000x reference)
#include <cuda_runtime.h>

#define NFFT 1024
#define NT   256
#define WARPS (NT / 32)

// exp(+2*pi*i*k/32), k = 0..15  (inverse-FFT sign)
__device__ const float TW32R[16] = {
    1.00000000f,  0.98078528f,  0.92387953f,  0.83146961f,
    0.70710678f,  0.55557023f,  0.38268343f,  0.19509032f,
    0.00000000f, -0.19509032f, -0.38268343f, -0.55557023f,
   -0.70710678f, -0.83146961f, -0.92387953f, -0.98078528f
};
__device__ const float TW32I[16] = {
    0.00000000f,  0.19509032f,  0.38268343f,  0.55557023f,
    0.70710678f,  0.83146961f,  0.92387953f,  0.98078528f,
    1.00000000f,  0.98078528f,  0.92387953f,  0.83146961f,
    0.70710678f,  0.55557023f,  0.38268343f,  0.19509032f
};

// In-register 32-point inverse DFT (unnormalized), natural in -> natural out.
// Fully unrolled radix-2 DIT; all indices & twiddles are compile-time constants.
__device__ __forceinline__ void fft32_reg(float vr[32], float vi[32])
{
    // bit-reversal (rev5) permutation
    #pragma unroll
    for (int i = 0; i < 32; i++) {
        int j = ((i & 1) << 4) | ((i & 2) << 2) | (i & 4) | ((i & 8) >> 2) | ((i & 16) >> 4);
        if (j > i) {
            float tr = vr[i]; vr[i] = vr[j]; vr[j] = tr;
            float ti = vi[i]; vi[i] = vi[j]; vi[j] = ti;
        }
    }
    #pragma unroll
    for (int h = 1; h < 32; h <<= 1) {
        #pragma unroll
        for (int g = 0; g < 32; g += 2 * h) {
            #pragma unroll
            for (int j = 0; j < h; j++) {
                const float wr = TW32R[j * (16 / h)];
                const float wi = TW32I[j * (16 / h)];
                const int a = g + j, b = g + j + h;
                float tr = vr[b] * wr - vi[b] * wi;
                float ti = vr[b] * wi + vi[b] * wr;
                vr[b] = vr[a] - tr;  vi[b] = vi[a] - ti;
                vr[a] = vr[a] + tr;  vi[a] = vi[a] + ti;
            }
        }
    }
}

// One warp per 1024-pt inverse FFT: 1024 = 32 x 32 Cooley-Tukey.
// Thread L: FFT32 over n2 of x[L + 32*n2]; twiddle W1024^(L*k2); swizzled
// 32x32 transpose via warp-private smem; FFT32 over n1; coalesced store.
__global__ __launch_bounds__(NT, 2) void ifft1024_warp(
    const float* __restrict__ re,
    const float* __restrict__ im,
    float* __restrict__ out_r,
    float* __restrict__ out_i)
{
    __shared__ float tbuf[WARPS][1024];   // 4KB per warp (re, then im, reused)

    const int lane = threadIdx.x & 31;
    const int w    = threadIdx.x >> 5;
    const long long row = (long long)blockIdx.x * WARPS + w;

    const float* xr = re + row * NFFT;
    const float* xi = im + row * NFFT;

    float vr[32], vi[32];

    // Coalesced loads: lanes stride-1, 32 rows apart per register slot.
    #pragma unroll
    for (int n2 = 0; n2 < 32; n2++) {
        vr[n2] = xr[lane + 32 * n2];
        vi[n2] = xi[lane + 32 * n2];
    }

    // Step 1: A[lane, k2] = sum_{n2} W32^{n2 k2} x[lane + 32 n2]
    fft32_reg(vr, vi);

    // Step 2: multiply by W1024^{lane * k2} = exp(+2*pi*i*lane*k2/1024).
    // One exact sincospif for the step; iterate powers (err ~3e-6 << 1e-3).
    {
        float sw, cw;
        sincospif((float)lane * (1.0f / 512.0f), &sw, &cw);
        float wr = 1.0f, wi = 0.0f;
        #pragma unroll
        for (int k2 = 0; k2 < 32; k2++) {
            float br = vr[k2] * wr - vi[k2] * wi;
            float bi = vr[k2] * wi + vi[k2] * wr;
            vr[k2] = br;  vi[k2] = bi;
            float nwr = wr * cw - wi * sw;
            wi = wr * sw + wi * cw;
            wr = nwr;
        }
    }

    // 32x32 transpose through warp-private shared, XOR-swizzled (conflict-free).
    float* buf = tbuf[w];
    #pragma unroll
    for (int k2 = 0; k2 < 32; k2++) buf[lane * 32 + (k2 ^ lane)] = vr[k2];
    __syncwarp();
    #pragma unroll
    for (int n1 = 0; n1 < 32; n1++) vr[n1] = buf[n1 * 32 + (lane ^ n1)];
    __syncwarp();
    #pragma unroll
    for (int k2 = 0; k2 < 32; k2++) buf[lane * 32 + (k2 ^ lane)] = vi[k2];
    __syncwarp();
    #pragma unroll
    for (int n1 = 0; n1 < 32; n1++) vi[n1] = buf[n1 * 32 + (lane ^ n1)];

    // Step 3: X[lane + 32 k1] = sum_{n1} W32^{n1 k1} B[n1, lane]
    fft32_reg(vr, vi);

    // Coalesced scaled stores.
    const float inv = 1.0f / (float)NFFT;
    float* orow  = out_r + row * NFFT;
    float* oirow = out_i + row * NFFT;
    #pragma unroll
    for (int k1 = 0; k1 < 32; k1++) {
        orow[lane + 32 * k1]  = vr[k1] * inv;
        oirow[lane + 32 * k1] = vi[k1] * inv;
    }
}

extern "C" void kernel_launch(void* const* d_in, const int* in_sizes, int n_in,
                              void* d_out, int out_size)
{
    const float* re = (const float*)d_in[0];
    const float* im = (const float*)d_in[1];
    float* out = (float*)d_out;

    const long long n_elems = (long long)in_sizes[0];   // 8*4096*1024
    const int nrows = (int)(n_elems / NFFT);            // 32768

    float* out_r = out;
    float* out_i = out + n_elems;                       // [yr | yi]

    ifft1024_warp<<<nrows / WARPS, NT>>>(re, im, out_r, out_i);
}